// round 16
// baseline (speedup 1.0000x reference)
#include <cuda_runtime.h>
#include <cuda_bf16.h>
#include <cstdint>

// Problem constants
#define BATCH   4
#define TSEQ    2048
#define CDIM    1024
#define NHEADS  16
#define HDIM    64
#define MROWS   (BATCH * TSEQ)     // 8192
#define NQKV    (3 * CDIM)         // 3072

// Scratch (allocation-free rule: __device__ globals)
__device__ float g_Q[(size_t)BATCH * NHEADS * TSEQ * HDIM];
__device__ float g_K[(size_t)BATCH * NHEADS * TSEQ * HDIM];
__device__ float g_V[(size_t)BATCH * NHEADS * TSEQ * HDIM];
__device__ float g_Y[(size_t)MROWS * CDIM];
// hi/lo split operands (separate arrays; no duplicated hi)
__device__ __nv_bfloat16 g_xh[(size_t)MROWS * CDIM];
__device__ __nv_bfloat16 g_xl[(size_t)MROWS * CDIM];
__device__ __nv_bfloat16 g_yh[(size_t)MROWS * CDIM];
__device__ __nv_bfloat16 g_yl[(size_t)MROWS * CDIM];
__device__ __nv_bfloat16 g_wqh[(size_t)NQKV * CDIM];   // w_qkv^T hi [n][k]
__device__ __nv_bfloat16 g_wql[(size_t)NQKV * CDIM];
__device__ __nv_bfloat16 g_wph[(size_t)CDIM * CDIM];   // w_proj^T hi [n][k]
__device__ __nv_bfloat16 g_wpl[(size_t)CDIM * CDIM];

// ---------------------------------------------------------------------------
// Warp-level MMA helpers (base sm_103-legal PTX: ldmatrix + mma.sync)
// ---------------------------------------------------------------------------
__device__ __forceinline__ uint32_t smem_u32(const void* p) {
    uint32_t a;
    asm("{ .reg .u64 t; cvta.to.shared.u64 t, %1; cvt.u32.u64 %0, t; }"
        : "=r"(a) : "l"(p));
    return a;
}

__device__ __forceinline__ void ldsm_x4(uint32_t& r0, uint32_t& r1,
                                        uint32_t& r2, uint32_t& r3, uint32_t addr) {
    asm volatile("ldmatrix.sync.aligned.m8n8.x4.shared.b16 {%0,%1,%2,%3}, [%4];"
                 : "=r"(r0), "=r"(r1), "=r"(r2), "=r"(r3) : "r"(addr));
}

__device__ __forceinline__ void ldsm_x2(uint32_t& r0, uint32_t& r1, uint32_t addr) {
    asm volatile("ldmatrix.sync.aligned.m8n8.x2.shared.b16 {%0,%1}, [%2];"
                 : "=r"(r0), "=r"(r1) : "r"(addr));
}

__device__ __forceinline__ void mma16816(float* c, const uint32_t* a,
                                         const uint32_t* b) {
    asm volatile(
        "mma.sync.aligned.m16n8k16.row.col.f32.bf16.bf16.f32 "
        "{%0,%1,%2,%3}, {%4,%5,%6,%7}, {%8,%9}, {%0,%1,%2,%3};"
        : "+f"(c[0]), "+f"(c[1]), "+f"(c[2]), "+f"(c[3])
        : "r"(a[0]), "r"(a[1]), "r"(a[2]), "r"(a[3]), "r"(b[0]), "r"(b[1]));
}

__device__ __forceinline__ void bsplit(float v, __nv_bfloat16& h, __nv_bfloat16& l) {
    h = __float2bfloat16(v);
    l = __float2bfloat16(v - __bfloat162float(h));
}

// ---------------------------------------------------------------------------
// Convert kernels: hi/lo split into separate arrays (contiguous writes)
// ---------------------------------------------------------------------------
__global__ __launch_bounds__(256) void convert_act(
    const float* __restrict__ a,
    __nv_bfloat16* __restrict__ ah, __nv_bfloat16* __restrict__ al)
{
    const size_t idx = (size_t)blockIdx.x * 256 + threadIdx.x;
    __nv_bfloat16 h, l;
    bsplit(a[idx], h, l);
    ah[idx] = h;
    al[idx] = l;
}

__global__ __launch_bounds__(256) void convert_wt(
    const float* __restrict__ w,
    __nv_bfloat16* __restrict__ wh, __nv_bfloat16* __restrict__ wl, const int Nw)
{
    __shared__ float t[32][33];
    const int k0 = blockIdx.x * 32;
    const int n0 = blockIdx.y * 32;
    const int tx = threadIdx.x & 31;
    const int ty = threadIdx.x >> 5;
#pragma unroll
    for (int i = 0; i < 4; i++)
        t[ty + i * 8][tx] = w[(size_t)(k0 + ty + i * 8) * Nw + n0 + tx];
    __syncthreads();
#pragma unroll
    for (int i = 0; i < 4; i++) {
        const int n = n0 + ty + i * 8;
        const int k = k0 + tx;
        __nv_bfloat16 h, l;
        bsplit(t[tx][ty + i * 8], h, l);
        wh[(size_t)n * CDIM + k] = h;
        wl[(size_t)n * CDIM + k] = l;
    }
}

// ---------------------------------------------------------------------------
// HMMA GEMM, hi/lo fragment-reuse: C = Ah*Bh + Ah*Bl + Al*Bh (+bias).
// 128x128 block, K=1024 in 32-chunks, 8 warps (2m x 4n), warp tile 64x32.
// ---------------------------------------------------------------------------
#define TSTRIDE 40
#define KC      32

__global__ __launch_bounds__(256) void mma_gemm(
    const __nv_bfloat16* __restrict__ Ah, const __nv_bfloat16* __restrict__ Al,
    const __nv_bfloat16* __restrict__ Bh, const __nv_bfloat16* __restrict__ Bl,
    const float* __restrict__ bias,
    float* __restrict__ Cout,
    const int scatter)
{
    __shared__ __align__(16) __nv_bfloat16 Ash[128 * TSTRIDE];
    __shared__ __align__(16) __nv_bfloat16 Asl[128 * TSTRIDE];
    __shared__ __align__(16) __nv_bfloat16 Bsh[128 * TSTRIDE];
    __shared__ __align__(16) __nv_bfloat16 Bsl[128 * TSTRIDE];

    const int tid  = threadIdx.x;
    const int wid  = tid >> 5;
    const int lane = tid & 31;
    const int row0 = blockIdx.y * 128;
    const int col0 = blockIdx.x * 128;

    const int wr = wid >> 2;
    const int wc = wid & 3;
    const int m0 = wr * 64;
    const int n0 = wc * 32;

    const int a_row = (lane & 7) + 8 * ((lane >> 3) & 1);
    const int a_col = 8 * (lane >> 4);
    const int b_row = lane & 7;
    const int b_col = 8 * ((lane >> 3) & 1);

    const uint32_t sAh = smem_u32(Ash);
    const uint32_t sAl = smem_u32(Asl);
    const uint32_t sBh = smem_u32(Bsh);
    const uint32_t sBl = smem_u32(Bsl);

    const int lrow = tid >> 2;            // 0..63
    const int lkg  = (tid & 3) * 8;       // 0,8,16,24

    const __nv_bfloat16* Agh = Ah + (size_t)row0 * CDIM;
    const __nv_bfloat16* Agl = Al + (size_t)row0 * CDIM;
    const __nv_bfloat16* Bgh = Bh + (size_t)col0 * CDIM;
    const __nv_bfloat16* Bgl = Bl + (size_t)col0 * CDIM;

    float acc[4][4][4] = {};

    float4 pf[8];
    pf[0] = *(const float4*)(Agh + (size_t)lrow * CDIM + lkg);
    pf[1] = *(const float4*)(Agh + (size_t)(lrow + 64) * CDIM + lkg);
    pf[2] = *(const float4*)(Agl + (size_t)lrow * CDIM + lkg);
    pf[3] = *(const float4*)(Agl + (size_t)(lrow + 64) * CDIM + lkg);
    pf[4] = *(const float4*)(Bgh + (size_t)lrow * CDIM + lkg);
    pf[5] = *(const float4*)(Bgh + (size_t)(lrow + 64) * CDIM + lkg);
    pf[6] = *(const float4*)(Bgl + (size_t)lrow * CDIM + lkg);
    pf[7] = *(const float4*)(Bgl + (size_t)(lrow + 64) * CDIM + lkg);

    for (int k0 = 0; k0 < CDIM; k0 += KC) {
        __syncthreads();
        *(float4*)(Ash + lrow * TSTRIDE + lkg)        = pf[0];
        *(float4*)(Ash + (lrow + 64) * TSTRIDE + lkg) = pf[1];
        *(float4*)(Asl + lrow * TSTRIDE + lkg)        = pf[2];
        *(float4*)(Asl + (lrow + 64) * TSTRIDE + lkg) = pf[3];
        *(float4*)(Bsh + lrow * TSTRIDE + lkg)        = pf[4];
        *(float4*)(Bsh + (lrow + 64) * TSTRIDE + lkg) = pf[5];
        *(float4*)(Bsl + lrow * TSTRIDE + lkg)        = pf[6];
        *(float4*)(Bsl + (lrow + 64) * TSTRIDE + lkg) = pf[7];
        __syncthreads();

        if (k0 + KC < CDIM) {
            const int kn = k0 + KC + lkg;
            pf[0] = *(const float4*)(Agh + (size_t)lrow * CDIM + kn);
            pf[1] = *(const float4*)(Agh + (size_t)(lrow + 64) * CDIM + kn);
            pf[2] = *(const float4*)(Agl + (size_t)lrow * CDIM + kn);
            pf[3] = *(const float4*)(Agl + (size_t)(lrow + 64) * CDIM + kn);
            pf[4] = *(const float4*)(Bgh + (size_t)lrow * CDIM + kn);
            pf[5] = *(const float4*)(Bgh + (size_t)(lrow + 64) * CDIM + kn);
            pf[6] = *(const float4*)(Bgl + (size_t)lrow * CDIM + kn);
            pf[7] = *(const float4*)(Bgl + (size_t)(lrow + 64) * CDIM + kn);
        }

#pragma unroll
        for (int ks = 0; ks < 2; ks++) {
            const int kb = ks * 16;
            uint32_t bfh[4][2], bfl[4][2];
#pragma unroll
            for (int j = 0; j < 4; j++) {
                const uint32_t off =
                    (uint32_t)(((n0 + 8 * j + b_row) * TSTRIDE + kb + b_col) * 2);
                ldsm_x2(bfh[j][0], bfh[j][1], sBh + off);
                ldsm_x2(bfl[j][0], bfl[j][1], sBl + off);
            }
#pragma unroll
            for (int i = 0; i < 4; i++) {
                const uint32_t off =
                    (uint32_t)(((m0 + 16 * i + a_row) * TSTRIDE + kb + a_col) * 2);
                uint32_t afh[4];
                ldsm_x4(afh[0], afh[1], afh[2], afh[3], sAh + off);
#pragma unroll
                for (int j = 0; j < 4; j++) {
                    mma16816(acc[i][j], afh, bfh[j]);
                    mma16816(acc[i][j], afh, bfl[j]);
                }
                uint32_t afl[4];
                ldsm_x4(afl[0], afl[1], afl[2], afl[3], sAl + off);
#pragma unroll
                for (int j = 0; j < 4; j++)
                    mma16816(acc[i][j], afl, bfh[j]);
            }
        }
    }

    const int g   = lane >> 2;
    const int tig = lane & 3;
#pragma unroll
    for (int i = 0; i < 4; i++) {
#pragma unroll
        for (int j = 0; j < 4; j++) {
            const int col = col0 + n0 + 8 * j + 2 * tig;
            const float bx = bias[col];
            const float by = bias[col + 1];
            const int r0 = row0 + m0 + 16 * i + g;
            const int r1 = r0 + 8;
            float2 v0 = make_float2(acc[i][j][0] + bx, acc[i][j][1] + by);
            float2 v1 = make_float2(acc[i][j][2] + bx, acc[i][j][3] + by);
            if (scatter) {
                const int s = col >> 10;
                const int h = (col & 1023) >> 6;
                const int d = col & 63;
                float* dst = (s == 0) ? g_Q : (s == 1) ? g_K : g_V;
                const int b0i = r0 >> 11, t0i = r0 & 2047;
                const int b1i = r1 >> 11, t1i = r1 & 2047;
                *(float2*)(dst + ((size_t)(b0i * NHEADS + h) * TSEQ + t0i) * HDIM + d) = v0;
                *(float2*)(dst + ((size_t)(b1i * NHEADS + h) * TSEQ + t1i) * HDIM + d) = v1;
            } else {
                *(float2*)(Cout + (size_t)r0 * CDIM + col) = v0;
                *(float2*)(Cout + (size_t)r1 * CDIM + col) = v1;
            }
        }
    }
}

// ---------------------------------------------------------------------------
// HMMA causal flash attention, hi/lo fragment-reuse.
// 128 q/block, 64-key tiles, 8 warps in 8m x 1n (warp-private softmax rows).
// smem (bf16, stride 72): Qh,Ql[128] | U { Kh,Kl[64] / Ph,Pl[128] } | Vh,Vl[64]
// ---------------------------------------------------------------------------
#define AST    72
#define AKT    64
#define A_QH   0
#define A_QL   (128 * AST)
#define A_U    (256 * AST)                 // Kh @ U, Kl @ U+64*AST; Ph @ U, Pl @ U+128*AST
#define A_VH   (512 * AST)
#define A_VL   (576 * AST)
#define A_SMEM_BYTES ((640 * AST) * 2)     // 92160 B

__global__ __launch_bounds__(256) void attn_mma()
{
    extern __shared__ __align__(16) __nv_bfloat16 smx[];
    __nv_bfloat16* Qh = smx + A_QH;
    __nv_bfloat16* Ql = smx + A_QL;
    __nv_bfloat16* Kh = smx + A_U;
    __nv_bfloat16* Kl = smx + A_U + 64 * AST;
    __nv_bfloat16* Ph = smx + A_U;
    __nv_bfloat16* Pl = smx + A_U + 128 * AST;
    __nv_bfloat16* Vh = smx + A_VH;
    __nv_bfloat16* Vl = smx + A_VL;

    const int tid  = threadIdx.x;
    const int wid  = tid >> 5;
    const int lane = tid & 31;
    const int m0w  = wid * 16;

    const int a_row = (lane & 7) + 8 * ((lane >> 3) & 1);
    const int a_col = 8 * (lane >> 4);
    const int b_row = lane & 7;
    const int b_col = 8 * ((lane >> 3) & 1);
    const int g     = lane >> 2;
    const int tig   = lane & 3;

    const uint32_t sQh = smem_u32(Qh);
    const uint32_t sQl = smem_u32(Ql);
    const uint32_t sKh = smem_u32(Kh);
    const uint32_t sKl = smem_u32(Kl);
    const uint32_t sPh = smem_u32(Ph);
    const uint32_t sPl = smem_u32(Pl);
    const uint32_t sVh = smem_u32(Vh);
    const uint32_t sVl = smem_u32(Vl);

    const int bh = blockIdx.y;
    const int q0 = blockIdx.x * 128;

    const float* Qg = g_Q + (size_t)bh * TSEQ * HDIM;
    const float* Kg = g_K + (size_t)bh * TSEQ * HDIM;
    const float* Vg = g_V + (size_t)bh * TSEQ * HDIM;

    const float scale = 0.125f;

    // Load Q (pre-scaled, split)
#pragma unroll
    for (int c = 0; c < 8; c++) {
        const int f  = c * 256 + tid;
        const int q  = f >> 4;
        const int dg = (f & 15) * 4;
        float4 v = *(const float4*)(Qg + (size_t)(q0 + q) * HDIM + dg);
        float vv[4] = {v.x, v.y, v.z, v.w};
#pragma unroll
        for (int e = 0; e < 4; e++) {
            __nv_bfloat16 h, l;
            bsplit(vv[e] * scale, h, l);
            Qh[q * AST + dg + e] = h;
            Ql[q * AST + dg + e] = l;
        }
    }

    float oacc[8][4] = {};
    float mrow[2] = {-1e30f, -1e30f};
    float lrow[2] = {};

    const int nkt = 2 * blockIdx.x + 2;

    for (int kt = 0; kt < nkt; kt++) {
        const int k0 = kt * AKT;
        __syncthreads();

        // Load K (split) and V (transposed, split)
#pragma unroll
        for (int c = 0; c < 4; c++) {
            const int f  = c * 256 + tid;
            const int kk = f >> 4;
            const int dg = (f & 15) * 4;
            float4 kv = *(const float4*)(Kg + (size_t)(k0 + kk) * HDIM + dg);
            float kvv[4] = {kv.x, kv.y, kv.z, kv.w};
#pragma unroll
            for (int e = 0; e < 4; e++) {
                __nv_bfloat16 h, l;
                bsplit(kvv[e], h, l);
                Kh[kk * AST + dg + e] = h;
                Kl[kk * AST + dg + e] = l;
            }
            float4 vv4 = *(const float4*)(Vg + (size_t)(k0 + kk) * HDIM + dg);
            float vvv[4] = {vv4.x, vv4.y, vv4.z, vv4.w};
#pragma unroll
            for (int e = 0; e < 4; e++) {
                __nv_bfloat16 h, l;
                bsplit(vvv[e], h, l);
                Vh[(dg + e) * AST + kk] = h;
                Vl[(dg + e) * AST + kk] = l;
            }
        }
        __syncthreads();

        // S = Qh*Kh^T + Qh*Kl^T + Ql*Kh^T : warp tile 16(q) x 64(key) x 64
        float sacc[8][4] = {};
#pragma unroll
        for (int ks = 0; ks < 4; ks++) {
            const int kb = ks * 16;
            const uint32_t aoff =
                (uint32_t)(((m0w + a_row) * AST + kb + a_col) * 2);
            uint32_t aqh[4], aql[4];
            ldsm_x4(aqh[0], aqh[1], aqh[2], aqh[3], sQh + aoff);
            ldsm_x4(aql[0], aql[1], aql[2], aql[3], sQl + aoff);
#pragma unroll
            for (int j = 0; j < 8; j++) {
                const uint32_t boff =
                    (uint32_t)(((8 * j + b_row) * AST + kb + b_col) * 2);
                uint32_t bh0, bh1, bl0, bl1;
                ldsm_x2(bh0, bh1, sKh + boff);
                ldsm_x2(bl0, bl1, sKl + boff);
                uint32_t bfh[2] = {bh0, bh1};
                uint32_t bfl[2] = {bl0, bl1};
                mma16816(sacc[j], aqh, bfh);
                mma16816(sacc[j], aqh, bfl);
                mma16816(sacc[j], aql, bfh);
            }
        }

        // Causal mask on diagonal-overlapping tiles
        if (k0 + AKT - 1 > q0) {
#pragma unroll
            for (int half = 0; half < 2; half++) {
                const int qrow = q0 + m0w + 8 * half + g;
#pragma unroll
                for (int j = 0; j < 8; j++)
#pragma unroll
                    for (int cc = 0; cc < 2; cc++) {
                        const int kcol = k0 + 8 * j + 2 * tig + cc;
                        if (kcol > qrow) sacc[j][2 * half + cc] = -1e30f;
                    }
            }
        }

        // Online softmax (warp-private rows; reduce over 4 tig lanes)
#pragma unroll
        for (int half = 0; half < 2; half++) {
            const int base = 2 * half;
            float mx = -1e30f;
#pragma unroll
            for (int j = 0; j < 8; j++)
                mx = fmaxf(mx, fmaxf(sacc[j][base], sacc[j][base + 1]));
            mx = fmaxf(mx, __shfl_xor_sync(0xffffffffu, mx, 1));
            mx = fmaxf(mx, __shfl_xor_sync(0xffffffffu, mx, 2));
            const float mnew = fmaxf(mrow[half], mx);
            float rs = 0.f;
#pragma unroll
            for (int j = 0; j < 8; j++) {
                const float p0 = __expf(sacc[j][base] - mnew);
                const float p1 = __expf(sacc[j][base + 1] - mnew);
                sacc[j][base] = p0;
                sacc[j][base + 1] = p1;
                rs += p0 + p1;
            }
            rs += __shfl_xor_sync(0xffffffffu, rs, 1);
            rs += __shfl_xor_sync(0xffffffffu, rs, 2);
            const float corr = __expf(mrow[half] - mnew);
            lrow[half] = lrow[half] * corr + rs;
            mrow[half] = mnew;
#pragma unroll
            for (int j = 0; j < 8; j++) {
                oacc[j][base] *= corr;
                oacc[j][base + 1] *= corr;
            }
        }

        __syncthreads();   // all S reads of Kh/Kl done before Ph/Pl overwrite

        // Write P split into Ph/Pl
        {
            const int r0 = m0w + g;
            const int r1 = m0w + 8 + g;
#pragma unroll
            for (int j = 0; j < 8; j++) {
                const int cc = 8 * j + 2 * tig;
#pragma unroll
                for (int c = 0; c < 2; c++) {
                    __nv_bfloat16 h, l;
                    bsplit(sacc[j][c], h, l);
                    Ph[r0 * AST + cc + c] = h;
                    Pl[r0 * AST + cc + c] = l;
                    bsplit(sacc[j][2 + c], h, l);
                    Ph[r1 * AST + cc + c] = h;
                    Pl[r1 * AST + cc + c] = l;
                }
            }
        }
        __syncthreads();

        // O += Ph*Vh + Ph*Vl + Pl*Vh : warp tile 16(q) x 64(d) x 64
#pragma unroll
        for (int ks = 0; ks < 4; ks++) {
            const int kb = ks * 16;
            const uint32_t aoff =
                (uint32_t)(((m0w + a_row) * AST + kb + a_col) * 2);
            uint32_t aph[4], apl[4];
            ldsm_x4(aph[0], aph[1], aph[2], aph[3], sPh + aoff);
            ldsm_x4(apl[0], apl[1], apl[2], apl[3], sPl + aoff);
#pragma unroll
            for (int j = 0; j < 8; j++) {
                const uint32_t boff =
                    (uint32_t)(((8 * j + b_row) * AST + kb + b_col) * 2);
                uint32_t bh0, bh1, bl0, bl1;
                ldsm_x2(bh0, bh1, sVh + boff);
                ldsm_x2(bl0, bl1, sVl + boff);
                uint32_t bfh[2] = {bh0, bh1};
                uint32_t bfl[2] = {bl0, bl1};
                mma16816(oacc[j], aph, bfh);
                mma16816(oacc[j], aph, bfl);
                mma16816(oacc[j], apl, bfh);
            }
        }
    }

    // Normalize and write to (B,T,C)
    const int b = bh >> 4;
    const int h = bh & 15;
#pragma unroll
    for (int half = 0; half < 2; half++) {
        const float inv = 1.0f / lrow[half];
        const int t = q0 + m0w + 8 * half + g;
#pragma unroll
        for (int j = 0; j < 8; j++) {
            const int d = 8 * j + 2 * tig;
            float2 v = make_float2(oacc[j][2 * half] * inv,
                                   oacc[j][2 * half + 1] * inv);
            *(float2*)(g_Y + (size_t)(b * TSEQ + t) * CDIM + h * HDIM + d) = v;
        }
    }
}

// ---------------------------------------------------------------------------
extern "C" void kernel_launch(void* const* d_in, const int* in_sizes, int n_in,
                              void* d_out, int out_size)
{
    const float* x      = (const float*)d_in[0];
    const float* w_qkv  = (const float*)d_in[1];
    const float* b_qkv  = (const float*)d_in[2];
    const float* w_proj = (const float*)d_in[3];
    const float* b_proj = (const float*)d_in[4];
    float* out = (float*)d_out;

    // Resolve true DEVICE addresses of host-passed __device__ globals.
    void *p_xh, *p_xl, *p_yh, *p_yl, *p_wqh, *p_wql, *p_wph, *p_wpl, *p_Y;
    cudaGetSymbolAddress(&p_xh, g_xh);
    cudaGetSymbolAddress(&p_xl, g_xl);
    cudaGetSymbolAddress(&p_yh, g_yh);
    cudaGetSymbolAddress(&p_yl, g_yl);
    cudaGetSymbolAddress(&p_wqh, g_wqh);
    cudaGetSymbolAddress(&p_wql, g_wql);
    cudaGetSymbolAddress(&p_wph, g_wph);
    cudaGetSymbolAddress(&p_wpl, g_wpl);
    cudaGetSymbolAddress(&p_Y,  g_Y);
    __nv_bfloat16* xh = (__nv_bfloat16*)p_xh;
    __nv_bfloat16* xl = (__nv_bfloat16*)p_xl;
    __nv_bfloat16* yh = (__nv_bfloat16*)p_yh;
    __nv_bfloat16* yl = (__nv_bfloat16*)p_yl;
    __nv_bfloat16* wqh = (__nv_bfloat16*)p_wqh;
    __nv_bfloat16* wql = (__nv_bfloat16*)p_wql;
    __nv_bfloat16* wph = (__nv_bfloat16*)p_wph;
    __nv_bfloat16* wpl = (__nv_bfloat16*)p_wpl;
    float* Yd = (float*)p_Y;

    cudaFuncSetAttribute(attn_mma,
                         cudaFuncAttributeMaxDynamicSharedMemorySize,
                         A_SMEM_BYTES);

    convert_act<<<(MROWS * CDIM) / 256, 256>>>(x, xh, xl);
    convert_wt<<<dim3(CDIM / 32, NQKV / 32), 256>>>(w_qkv, wqh, wql, NQKV);
    convert_wt<<<dim3(CDIM / 32, CDIM / 32), 256>>>(w_proj, wph, wpl, CDIM);

    mma_gemm<<<dim3(NQKV / 128, MROWS / 128), 256>>>(xh, xl, wqh, wql,
                                                     b_qkv, nullptr, 1);
    attn_mma<<<dim3(TSEQ / 128, BATCH * NHEADS), 256, A_SMEM_BYTES>>>();
    convert_act<<<(MROWS * CDIM) / 256, 256>>>(Yd, yh, yl);
    mma_gemm<<<dim3(CDIM / 128, MROWS / 128), 256>>>(yh, yl, wph, wpl,
                                                     b_proj, out, 0);
}

// round 17
// speedup vs baseline: 1.3106x; 1.3106x over previous
#include <cuda_runtime.h>
#include <cuda_bf16.h>
#include <cstdint>

// Problem constants
#define BATCH   4
#define TSEQ    2048
#define CDIM    1024
#define NHEADS  16
#define HDIM    64
#define MROWS   (BATCH * TSEQ)     // 8192
#define NQKV    (3 * CDIM)         // 3072
#define KEXP    (3 * CDIM)         // bf16x3 expanded reduction dim

// Scratch (allocation-free rule: __device__ globals)
__device__ float g_Q[(size_t)BATCH * NHEADS * TSEQ * HDIM];
__device__ float g_K[(size_t)BATCH * NHEADS * TSEQ * HDIM];
__device__ float g_V[(size_t)BATCH * NHEADS * TSEQ * HDIM];
__device__ float g_Y[(size_t)MROWS * CDIM];
// bf16x3-expanded operands
__device__ __nv_bfloat16 g_xe[(size_t)MROWS * KEXP];
__device__ __nv_bfloat16 g_ye[(size_t)MROWS * KEXP];
__device__ __nv_bfloat16 g_wqkv_t[(size_t)NQKV * KEXP];
__device__ __nv_bfloat16 g_wproj_t[(size_t)CDIM * KEXP];

// ---------------------------------------------------------------------------
// Warp-level MMA helpers (base sm_103-legal PTX)
// ---------------------------------------------------------------------------
__device__ __forceinline__ uint32_t smem_u32(const void* p) {
    uint32_t a;
    asm("{ .reg .u64 t; cvta.to.shared.u64 t, %1; cvt.u32.u64 %0, t; }"
        : "=r"(a) : "l"(p));
    return a;
}

__device__ __forceinline__ void ldsm_x4(uint32_t& r0, uint32_t& r1,
                                        uint32_t& r2, uint32_t& r3, uint32_t addr) {
    asm volatile("ldmatrix.sync.aligned.m8n8.x4.shared.b16 {%0,%1,%2,%3}, [%4];"
                 : "=r"(r0), "=r"(r1), "=r"(r2), "=r"(r3) : "r"(addr));
}

__device__ __forceinline__ void ldsm_x2(uint32_t& r0, uint32_t& r1, uint32_t addr) {
    asm volatile("ldmatrix.sync.aligned.m8n8.x2.shared.b16 {%0,%1}, [%2];"
                 : "=r"(r0), "=r"(r1) : "r"(addr));
}

__device__ __forceinline__ void mma16816(float* c, const uint32_t* a,
                                         const uint32_t* b) {
    asm volatile(
        "mma.sync.aligned.m16n8k16.row.col.f32.bf16.bf16.f32 "
        "{%0,%1,%2,%3}, {%4,%5,%6,%7}, {%8,%9}, {%0,%1,%2,%3};"
        : "+f"(c[0]), "+f"(c[1]), "+f"(c[2]), "+f"(c[3])
        : "r"(a[0]), "r"(a[1]), "r"(a[2]), "r"(a[3]), "r"(b[0]), "r"(b[1]));
}

__device__ __forceinline__ void bsplit(float v, __nv_bfloat16& h, __nv_bfloat16& l) {
    h = __float2bfloat16(v);
    l = __float2bfloat16(v - __bfloat162float(h));
}

__device__ __forceinline__ void cp16(uint32_t saddr, const void* gptr) {
    asm volatile("cp.async.cg.shared.global [%0], [%1], 16;"
                 :: "r"(saddr), "l"(gptr) : "memory");
}
#define CP_COMMIT() asm volatile("cp.async.commit_group;" ::: "memory")
#define CP_WAIT_1() asm volatile("cp.async.wait_group 1;" ::: "memory")
#define CP_WAIT_0() asm volatile("cp.async.wait_group 0;" ::: "memory")

// ---------------------------------------------------------------------------
// Convert kernels (bf16x3 expansion): A blocks [hi,hi,lo]; B blocks [hi,lo,hi]
// ---------------------------------------------------------------------------
__global__ __launch_bounds__(256) void convert_act(
    const float* __restrict__ a, __nv_bfloat16* __restrict__ ae)
{
    const size_t idx = (size_t)blockIdx.x * 256 + threadIdx.x;
    const int m = (int)(idx >> 10);
    const int k = (int)(idx & 1023);
    __nv_bfloat16 hi, lo;
    bsplit(a[idx], hi, lo);
    const size_t base = (size_t)m * KEXP;
    ae[base + k]            = hi;
    ae[base + CDIM + k]     = hi;
    ae[base + 2 * CDIM + k] = lo;
}

__global__ __launch_bounds__(256) void convert_wt(
    const float* __restrict__ w, __nv_bfloat16* __restrict__ wt, const int Nw)
{
    __shared__ float t[32][33];
    const int k0 = blockIdx.x * 32;
    const int n0 = blockIdx.y * 32;
    const int tx = threadIdx.x & 31;
    const int ty = threadIdx.x >> 5;
#pragma unroll
    for (int i = 0; i < 4; i++)
        t[ty + i * 8][tx] = w[(size_t)(k0 + ty + i * 8) * Nw + n0 + tx];
    __syncthreads();
#pragma unroll
    for (int i = 0; i < 4; i++) {
        const int n = n0 + ty + i * 8;
        const int k = k0 + tx;
        __nv_bfloat16 hi, lo;
        bsplit(t[tx][ty + i * 8], hi, lo);
        const size_t base = (size_t)n * KEXP;
        wt[base + k]            = hi;
        wt[base + CDIM + k]     = lo;
        wt[base + 2 * CDIM + k] = hi;
    }
}

// ---------------------------------------------------------------------------
// HMMA GEMM with cp.async double-buffered smem.
// C[128x128] = Ae[128 x K'] * Be[n][K']^T (+bias), K' = 3072, KC=32 chunks.
// 8 warps (2m x 4n), warp tile 64x32, mma.m16n8k16 bf16.
// ---------------------------------------------------------------------------
#define TSTRIDE 40
#define KC      32
#define NCHUNK  (KEXP / KC)          // 96
#define BUFB    (128 * TSTRIDE * 2)  // bytes per smem buffer

__global__ __launch_bounds__(256) void mma_gemm(
    const __nv_bfloat16* __restrict__ Ae,
    const __nv_bfloat16* __restrict__ Be,
    const float* __restrict__ bias,
    float* __restrict__ Cout,
    const int scatter)
{
    __shared__ __align__(16) __nv_bfloat16 As[2][128 * TSTRIDE];
    __shared__ __align__(16) __nv_bfloat16 Bs[2][128 * TSTRIDE];

    const int tid  = threadIdx.x;
    const int wid  = tid >> 5;
    const int lane = tid & 31;
    const int row0 = blockIdx.y * 128;
    const int col0 = blockIdx.x * 128;

    const int wr = wid >> 2;
    const int wc = wid & 3;
    const int m0 = wr * 64;
    const int n0 = wc * 32;

    const int a_row = (lane & 7) + 8 * ((lane >> 3) & 1);
    const int a_col = 8 * (lane >> 4);
    const int b_row = lane & 7;
    const int b_col = 8 * ((lane >> 3) & 1);

    const uint32_t sA0 = smem_u32(As);
    const uint32_t sB0 = smem_u32(Bs);

    const int lrow = tid >> 2;            // 0..63
    const int lkg  = (tid & 3) * 8;       // 0,8,16,24

    const __nv_bfloat16* Ag = Ae + (size_t)row0 * KEXP;
    const __nv_bfloat16* Bg = Be + (size_t)col0 * KEXP;

    float acc[4][4][4] = {};

    auto issue = [&](int ch, int buf) {
        const int kg = ch * KC + lkg;
        const uint32_t da = sA0 + (uint32_t)buf * BUFB + (lrow * TSTRIDE + lkg) * 2;
        cp16(da, Ag + (size_t)lrow * KEXP + kg);
        cp16(da + 64 * TSTRIDE * 2, Ag + (size_t)(lrow + 64) * KEXP + kg);
        const uint32_t db = sB0 + (uint32_t)buf * BUFB + (lrow * TSTRIDE + lkg) * 2;
        cp16(db, Bg + (size_t)lrow * KEXP + kg);
        cp16(db + 64 * TSTRIDE * 2, Bg + (size_t)(lrow + 64) * KEXP + kg);
    };

    issue(0, 0);
    CP_COMMIT();

    for (int ch = 0; ch < NCHUNK; ch++) {
        const int buf = ch & 1;
        if (ch + 1 < NCHUNK) {
            issue(ch + 1, buf ^ 1);
            CP_COMMIT();
            CP_WAIT_1();
        } else {
            CP_WAIT_0();
        }
        __syncthreads();

        const uint32_t sA = sA0 + (uint32_t)buf * BUFB;
        const uint32_t sB = sB0 + (uint32_t)buf * BUFB;
#pragma unroll
        for (int ks = 0; ks < 2; ks++) {
            const int kb = ks * 16;
            uint32_t af[4][4];
#pragma unroll
            for (int i = 0; i < 4; i++) {
                const uint32_t addr =
                    sA + (uint32_t)(((m0 + 16 * i + a_row) * TSTRIDE + kb + a_col) * 2);
                ldsm_x4(af[i][0], af[i][1], af[i][2], af[i][3], addr);
            }
            uint32_t bf[4][2];
#pragma unroll
            for (int j = 0; j < 4; j++) {
                const uint32_t addr =
                    sB + (uint32_t)(((n0 + 8 * j + b_row) * TSTRIDE + kb + b_col) * 2);
                ldsm_x2(bf[j][0], bf[j][1], addr);
            }
#pragma unroll
            for (int i = 0; i < 4; i++)
#pragma unroll
                for (int j = 0; j < 4; j++)
                    mma16816(acc[i][j], af[i], bf[j]);
        }
        __syncthreads();   // compute done before this buffer is refilled
    }

    const int g   = lane >> 2;
    const int tig = lane & 3;
#pragma unroll
    for (int i = 0; i < 4; i++) {
#pragma unroll
        for (int j = 0; j < 4; j++) {
            const int col = col0 + n0 + 8 * j + 2 * tig;
            const float bx = bias[col];
            const float by = bias[col + 1];
            const int r0 = row0 + m0 + 16 * i + g;
            const int r1 = r0 + 8;
            float2 v0 = make_float2(acc[i][j][0] + bx, acc[i][j][1] + by);
            float2 v1 = make_float2(acc[i][j][2] + bx, acc[i][j][3] + by);
            if (scatter) {
                const int s = col >> 10;
                const int h = (col & 1023) >> 6;
                const int d = col & 63;
                float* dst = (s == 0) ? g_Q : (s == 1) ? g_K : g_V;
                const int b0i = r0 >> 11, t0i = r0 & 2047;
                const int b1i = r1 >> 11, t1i = r1 & 2047;
                *(float2*)(dst + ((size_t)(b0i * NHEADS + h) * TSEQ + t0i) * HDIM + d) = v0;
                *(float2*)(dst + ((size_t)(b1i * NHEADS + h) * TSEQ + t1i) * HDIM + d) = v1;
            } else {
                *(float2*)(Cout + (size_t)r0 * CDIM + col) = v0;
                *(float2*)(Cout + (size_t)r1 * CDIM + col) = v1;
            }
        }
    }
}

// ---------------------------------------------------------------------------
// HMMA causal flash attention (identical to R15, passing at ~700us).
// 128 q/block, 64-key tiles, bf16x3 (k'=192), 8 warps 8m x 1n.
// ---------------------------------------------------------------------------
#define AQ_STR 200
#define AKT    64
#define A_SMEM_BF16 (320 * AQ_STR)
#define A_SMEM_BYTES (A_SMEM_BF16 * 2)        // 128000 B

__global__ __launch_bounds__(256) void attn_mma()
{
    extern __shared__ __align__(16) __nv_bfloat16 smx[];
    __nv_bfloat16* Qe = smx;                  // [128][200]  [qh|qh|ql]
    __nv_bfloat16* Ke = smx + 128 * AQ_STR;   // [64][200]   [kh|kl|kh]
    __nv_bfloat16* Pt = smx + 128 * AQ_STR;   // [128][200]  [ph|ph|pl] (aliases Ke)
    __nv_bfloat16* Vt = smx + 256 * AQ_STR;   // [64 d][200] [vh|vl|vh]

    const int tid  = threadIdx.x;
    const int wid  = tid >> 5;
    const int lane = tid & 31;
    const int m0w  = wid * 16;

    const int a_row = (lane & 7) + 8 * ((lane >> 3) & 1);
    const int a_col = 8 * (lane >> 4);
    const int b_row = lane & 7;
    const int b_col = 8 * ((lane >> 3) & 1);
    const int g     = lane >> 2;
    const int tig   = lane & 3;

    const uint32_t sQ = smem_u32(Qe);
    const uint32_t sK = smem_u32(Ke);
    const uint32_t sP = smem_u32(Pt);
    const uint32_t sV = smem_u32(Vt);

    const int bh = blockIdx.y;
    const int q0 = blockIdx.x * 128;

    const float* Qg = g_Q + (size_t)bh * TSEQ * HDIM;
    const float* Kg = g_K + (size_t)bh * TSEQ * HDIM;
    const float* Vg = g_V + (size_t)bh * TSEQ * HDIM;

    const float scale = 0.125f;

#pragma unroll
    for (int c = 0; c < 8; c++) {
        const int f  = c * 256 + tid;
        const int q  = f >> 4;
        const int dg = (f & 15) * 4;
        float4 v = *(const float4*)(Qg + (size_t)(q0 + q) * HDIM + dg);
        float vv[4] = {v.x, v.y, v.z, v.w};
#pragma unroll
        for (int e = 0; e < 4; e++) {
            __nv_bfloat16 h, l;
            bsplit(vv[e] * scale, h, l);
            Qe[q * AQ_STR + dg + e]       = h;
            Qe[q * AQ_STR + 64 + dg + e]  = h;
            Qe[q * AQ_STR + 128 + dg + e] = l;
        }
    }

    float oacc[8][4] = {};
    float mrow[2] = {-1e30f, -1e30f};
    float lrow[2] = {};

    const int nkt = 2 * blockIdx.x + 2;

    for (int kt = 0; kt < nkt; kt++) {
        const int k0 = kt * AKT;
        __syncthreads();

#pragma unroll
        for (int c = 0; c < 4; c++) {
            const int f  = c * 256 + tid;
            const int kk = f >> 4;
            const int dg = (f & 15) * 4;
            float4 kv = *(const float4*)(Kg + (size_t)(k0 + kk) * HDIM + dg);
            float kvv[4] = {kv.x, kv.y, kv.z, kv.w};
#pragma unroll
            for (int e = 0; e < 4; e++) {
                __nv_bfloat16 h, l;
                bsplit(kvv[e], h, l);
                Ke[kk * AQ_STR + dg + e]       = h;
                Ke[kk * AQ_STR + 64 + dg + e]  = l;
                Ke[kk * AQ_STR + 128 + dg + e] = h;
            }
            float4 vv4 = *(const float4*)(Vg + (size_t)(k0 + kk) * HDIM + dg);
            float vvv[4] = {vv4.x, vv4.y, vv4.z, vv4.w};
#pragma unroll
            for (int e = 0; e < 4; e++) {
                __nv_bfloat16 h, l;
                bsplit(vvv[e], h, l);
                Vt[(dg + e) * AQ_STR + kk]       = h;
                Vt[(dg + e) * AQ_STR + 64 + kk]  = l;
                Vt[(dg + e) * AQ_STR + 128 + kk] = h;
            }
        }
        __syncthreads();

        float sacc[8][4] = {};
#pragma unroll
        for (int ks = 0; ks < 12; ks++) {
            const int kb = ks * 16;
            uint32_t af[4];
            {
                const uint32_t addr =
                    sQ + (uint32_t)(((m0w + a_row) * AQ_STR + kb + a_col) * 2);
                ldsm_x4(af[0], af[1], af[2], af[3], addr);
            }
#pragma unroll
            for (int j = 0; j < 8; j++) {
                uint32_t b0, b1;
                const uint32_t addr =
                    sK + (uint32_t)(((8 * j + b_row) * AQ_STR + kb + b_col) * 2);
                ldsm_x2(b0, b1, addr);
                uint32_t bf2[2] = {b0, b1};
                mma16816(sacc[j], af, bf2);
            }
        }

        if (k0 + AKT - 1 > q0) {
#pragma unroll
            for (int half = 0; half < 2; half++) {
                const int qrow = q0 + m0w + 8 * half + g;
#pragma unroll
                for (int j = 0; j < 8; j++)
#pragma unroll
                    for (int cc = 0; cc < 2; cc++) {
                        const int kcol = k0 + 8 * j + 2 * tig + cc;
                        if (kcol > qrow) sacc[j][2 * half + cc] = -1e30f;
                    }
            }
        }

#pragma unroll
        for (int half = 0; half < 2; half++) {
            const int base = 2 * half;
            float mx = -1e30f;
#pragma unroll
            for (int j = 0; j < 8; j++)
                mx = fmaxf(mx, fmaxf(sacc[j][base], sacc[j][base + 1]));
            mx = fmaxf(mx, __shfl_xor_sync(0xffffffffu, mx, 1));
            mx = fmaxf(mx, __shfl_xor_sync(0xffffffffu, mx, 2));
            const float mnew = fmaxf(mrow[half], mx);
            float rs = 0.f;
#pragma unroll
            for (int j = 0; j < 8; j++) {
                const float p0 = __expf(sacc[j][base] - mnew);
                const float p1 = __expf(sacc[j][base + 1] - mnew);
                sacc[j][base] = p0;
                sacc[j][base + 1] = p1;
                rs += p0 + p1;
            }
            rs += __shfl_xor_sync(0xffffffffu, rs, 1);
            rs += __shfl_xor_sync(0xffffffffu, rs, 2);
            const float corr = __expf(mrow[half] - mnew);
            lrow[half] = lrow[half] * corr + rs;
            mrow[half] = mnew;
#pragma unroll
            for (int j = 0; j < 8; j++) {
                oacc[j][base] *= corr;
                oacc[j][base + 1] *= corr;
            }
        }

        __syncthreads();

        {
            const int r0 = m0w + g;
            const int r1 = m0w + 8 + g;
#pragma unroll
            for (int j = 0; j < 8; j++) {
                const int cc = 8 * j + 2 * tig;
#pragma unroll
                for (int c = 0; c < 2; c++) {
                    __nv_bfloat16 h, l;
                    bsplit(sacc[j][c], h, l);
                    Pt[r0 * AQ_STR + cc + c]       = h;
                    Pt[r0 * AQ_STR + 64 + cc + c]  = h;
                    Pt[r0 * AQ_STR + 128 + cc + c] = l;
                    bsplit(sacc[j][2 + c], h, l);
                    Pt[r1 * AQ_STR + cc + c]       = h;
                    Pt[r1 * AQ_STR + 64 + cc + c]  = h;
                    Pt[r1 * AQ_STR + 128 + cc + c] = l;
                }
            }
        }
        __syncthreads();

#pragma unroll
        for (int ks = 0; ks < 12; ks++) {
            const int kb = ks * 16;
            uint32_t af[4];
            {
                const uint32_t addr =
                    sP + (uint32_t)(((m0w + a_row) * AQ_STR + kb + a_col) * 2);
                ldsm_x4(af[0], af[1], af[2], af[3], addr);
            }
#pragma unroll
            for (int j = 0; j < 8; j++) {
                uint32_t b0, b1;
                const uint32_t addr =
                    sV + (uint32_t)(((8 * j + b_row) * AQ_STR + kb + b_col) * 2);
                ldsm_x2(b0, b1, addr);
                uint32_t bf2[2] = {b0, b1};
                mma16816(oacc[j], af, bf2);
            }
        }
    }

    const int b = bh >> 4;
    const int h = bh & 15;
#pragma unroll
    for (int half = 0; half < 2; half++) {
        const float inv = 1.0f / lrow[half];
        const int t = q0 + m0w + 8 * half + g;
#pragma unroll
        for (int j = 0; j < 8; j++) {
            const int d = 8 * j + 2 * tig;
            float2 v = make_float2(oacc[j][2 * half] * inv,
                                   oacc[j][2 * half + 1] * inv);
            *(float2*)(g_Y + (size_t)(b * TSEQ + t) * CDIM + h * HDIM + d) = v;
        }
    }
}

// ---------------------------------------------------------------------------
extern "C" void kernel_launch(void* const* d_in, const int* in_sizes, int n_in,
                              void* d_out, int out_size)
{
    const float* x      = (const float*)d_in[0];
    const float* w_qkv  = (const float*)d_in[1];
    const float* b_qkv  = (const float*)d_in[2];
    const float* w_proj = (const float*)d_in[3];
    const float* b_proj = (const float*)d_in[4];
    float* out = (float*)d_out;

    // Resolve true DEVICE addresses of host-passed __device__ globals.
    void *p_xe, *p_ye, *p_wq, *p_wp, *p_Y;
    cudaGetSymbolAddress(&p_xe, g_xe);
    cudaGetSymbolAddress(&p_ye, g_ye);
    cudaGetSymbolAddress(&p_wq, g_wqkv_t);
    cudaGetSymbolAddress(&p_wp, g_wproj_t);
    cudaGetSymbolAddress(&p_Y,  g_Y);
    __nv_bfloat16* xe = (__nv_bfloat16*)p_xe;
    __nv_bfloat16* ye = (__nv_bfloat16*)p_ye;
    __nv_bfloat16* wq = (__nv_bfloat16*)p_wq;
    __nv_bfloat16* wp = (__nv_bfloat16*)p_wp;
    float* Yd = (float*)p_Y;

    cudaFuncSetAttribute(attn_mma,
                         cudaFuncAttributeMaxDynamicSharedMemorySize,
                         A_SMEM_BYTES);

    convert_act<<<(MROWS * CDIM) / 256, 256>>>(x, xe);
    convert_wt<<<dim3(CDIM / 32, NQKV / 32), 256>>>(w_qkv, wq, NQKV);
    convert_wt<<<dim3(CDIM / 32, CDIM / 32), 256>>>(w_proj, wp, CDIM);

    mma_gemm<<<dim3(NQKV / 128, MROWS / 128), 256>>>(xe, wq, b_qkv, nullptr, 1);
    attn_mma<<<dim3(TSEQ / 128, BATCH * NHEADS), 256, A_SMEM_BYTES>>>();
    convert_act<<<(MROWS * CDIM) / 256, 256>>>(Yd, ye);
    mma_gemm<<<dim3(CDIM / 128, MROWS / 128), 256>>>(ye, wp, b_proj, out, 0);
}